// round 7
// baseline (speedup 1.0000x reference)
#include <cuda_runtime.h>

// q,k,v,out: (B=4, S=4096, H=16, D=64) f32. Hilbert gather + inverse scatter
// cancel (attention is strictly per-position): per (b,s) two independent 8x8
// head-vs-head attentions (groups of 8 heads), inner dim 64.
//
// R5: warp = (position, group). Lane (i = lane>>2, c = lane&3) owns q row i,
// 16-dim chunk c, in registers (strided LDG). k and v are NEVER staged: the
// score and AV loops read them straight from global with broadcast LDG.128
// (4 distinct 16B addresses/instr = 1 L1 wavefront; every sector fetched from
// DRAM exactly once). Scores reduced over the 4 c-lanes with 2 shfl per j,
// softmax fully local (row replicated across c-lanes), AV local.
#define NPOS  16384
#define SCALE 0.125f

__global__ __launch_bounds__(256)
void hilbert_headattn_kernel(const float4* __restrict__ q,
                             const float4* __restrict__ k,
                             const float4* __restrict__ v,
                             float4* __restrict__ out)
{
    const int lane = threadIdx.x & 31;
    const int wid  = blockIdx.x * 8 + (threadIdx.x >> 5);
    const int pos  = wid >> 1;
    const int g    = wid & 1;
    const int i    = lane >> 2;     // head row owned by this lane
    const int c    = lane & 3;      // 16-float chunk owned by this lane

    // float4 base of this warp's (pos, group) tile: 256 float4 per position
    const int tbase = pos * 256 + g * 128;
    // this lane's q/out chunk: row i (16 float4 per row), chunk c (4 float4)
    const int qbase = tbase + i * 16 + c * 4;
    // broadcast base for k/v rows: + j*16 + c*4 + m
    const int kcbase = tbase + c * 4;

    // ---- q chunk into registers (strided, sector-complete), fold SCALE ----
    float qr[16];
#pragma unroll
    for (int m = 0; m < 4; m++) {
        const float4 t = q[qbase + m];
        qr[4*m]   = t.x * SCALE;
        qr[4*m+1] = t.y * SCALE;
        qr[4*m+2] = t.z * SCALE;
        qr[4*m+3] = t.w * SCALE;
    }

    // ---- scores: s[j] = q[i] . k[j], k read broadcast from global ----
    float s[8];
#pragma unroll
    for (int j = 0; j < 8; j++) {
        float acc = 0.f;
#pragma unroll
        for (int m = 0; m < 4; m++) {
            const float4 t = k[kcbase + j * 16 + m];
            acc = fmaf(qr[4*m],   t.x, acc);
            acc = fmaf(qr[4*m+1], t.y, acc);
            acc = fmaf(qr[4*m+2], t.z, acc);
            acc = fmaf(qr[4*m+3], t.w, acc);
        }
        // sum partials over the 4 c-lanes of head i (lanes differ in bits 0,1)
        acc += __shfl_xor_sync(0xffffffffu, acc, 1);
        acc += __shfl_xor_sync(0xffffffffu, acc, 2);
        s[j] = acc;
    }

    // ---- softmax over j, fully local (row i replicated across c-lanes) ----
    float mx = s[0];
#pragma unroll
    for (int j = 1; j < 8; j++) mx = fmaxf(mx, s[j]);
    float sum = 0.f;
#pragma unroll
    for (int j = 0; j < 8; j++) { s[j] = __expf(s[j] - mx); sum += s[j]; }
    const float inv = __frcp_rn(sum);
#pragma unroll
    for (int j = 0; j < 8; j++) s[j] *= inv;

    // ---- AV: out[i, chunk c] = sum_j s[j] * v[j, chunk c] (v broadcast) ----
    float o[16];
#pragma unroll
    for (int m = 0; m < 16; m++) o[m] = 0.f;
#pragma unroll
    for (int j = 0; j < 8; j++) {
        const float a = s[j];
#pragma unroll
        for (int m = 0; m < 4; m++) {
            const float4 t = v[kcbase + j * 16 + m];
            o[4*m]   = fmaf(a, t.x, o[4*m]);
            o[4*m+1] = fmaf(a, t.y, o[4*m+1]);
            o[4*m+2] = fmaf(a, t.z, o[4*m+2]);
            o[4*m+3] = fmaf(a, t.w, o[4*m+3]);
        }
    }

#pragma unroll
    for (int m = 0; m < 4; m++)
        out[qbase + m] = make_float4(o[4*m], o[4*m+1], o[4*m+2], o[4*m+3]);
}

extern "C" void kernel_launch(void* const* d_in, const int* in_sizes, int n_in,
                              void* d_out, int out_size)
{
    const float4* q = (const float4*)d_in[0];
    const float4* k = (const float4*)d_in[1];
    const float4* v = (const float4*)d_in[2];
    float4* o       = (float4*)d_out;
    // 256 threads = 8 warps; 2 warps (head groups) per position; 4 pos per CTA
    hilbert_headattn_kernel<<<NPOS / 4, 256>>>(q, k, v, o);
}

// round 10
// speedup vs baseline: 1.8682x; 1.8682x over previous
#include <cuda_runtime.h>

// q,k,v,out: (B=4, S=4096, H=16, D=64) f32. Hilbert gather + inverse scatter
// cancel (attention is strictly per-position): per (b,s) two independent 8x8
// head-vs-head attentions (groups of 8 heads), inner dim 64.
//
// R6: warp = (position, group); lane (i = lane>>2, c = lane&3) owns q row i,
// chunk c (16 floats) in registers. k,v staged in WARP-PRIVATE smem arranged
// as 4 chunk-planes (plane stride 33 float4 => the 4 broadcast addresses per
// LDS.128 hit distinct banks). Scores: LDS broadcast + 2-shfl reduce.
// Softmax fully local. AV: LDS broadcast of v. No __syncthreads anywhere.
#define NPOS   16384
#define SCALE  0.125f
#define PLANE4 33                 // float4 stride of a chunk plane (8 rows * 4 + 1 pad)
#define WSLOT4 (2 * 4 * PLANE4)   // 264 float4 per warp (k: 132, v: 132)

__global__ __launch_bounds__(256)
void hilbert_headattn_kernel(const float4* __restrict__ q,
                             const float4* __restrict__ k,
                             const float4* __restrict__ v,
                             float4* __restrict__ out)
{
    __shared__ float4 skv[8 * WSLOT4];          // 33792 B, warp-private slots

    const int lane = threadIdx.x & 31;
    const int warp = threadIdx.x >> 5;
    const int wid  = blockIdx.x * 8 + warp;
    const int pos  = wid >> 1;
    const int g    = wid & 1;
    const int i    = lane >> 2;                 // head row owned by this lane
    const int c    = lane & 3;                  // 16-float chunk owned

    // global float4 base of this lane's (row i, chunk c) within the tile
    const int tbase = pos * 256 + g * 128;
    const int qbase = tbase + i * 16 + c * 4;

    float4* const wk = skv + warp * WSLOT4 + c * PLANE4;            // k planes
    float4* const wv = wk + 4 * PLANE4;                             // v planes

    // ---- load q (regs, SCALE folded) and stage k,v into smem planes ----
    float qr[16];
#pragma unroll
    for (int m = 0; m < 4; m++) {
        const float4 t = q[qbase + m];
        qr[4*m]   = t.x * SCALE;
        qr[4*m+1] = t.y * SCALE;
        qr[4*m+2] = t.z * SCALE;
        qr[4*m+3] = t.w * SCALE;
        wk[i * 4 + m] = k[qbase + m];   // lane (i,c) -> plane c, row i
        wv[i * 4 + m] = v[qbase + m];
    }
    __syncwarp();

    // ---- scores: s[j] = q[i] . k[j]  (k chunk c broadcast from smem) ----
    float s[8];
#pragma unroll
    for (int j = 0; j < 8; j++) {
        float acc = 0.f;
#pragma unroll
        for (int m = 0; m < 4; m++) {
            const float4 t = wk[j * 4 + m];
            acc = fmaf(qr[4*m],   t.x, acc);
            acc = fmaf(qr[4*m+1], t.y, acc);
            acc = fmaf(qr[4*m+2], t.z, acc);
            acc = fmaf(qr[4*m+3], t.w, acc);
        }
        // sum partials over the 4 c-lanes of head i (lane bits 0,1)
        acc += __shfl_xor_sync(0xffffffffu, acc, 1);
        acc += __shfl_xor_sync(0xffffffffu, acc, 2);
        s[j] = acc;
    }

    // ---- softmax over j, fully local (row replicated across c-lanes) ----
    float mx = s[0];
#pragma unroll
    for (int j = 1; j < 8; j++) mx = fmaxf(mx, s[j]);
    float sum = 0.f;
#pragma unroll
    for (int j = 0; j < 8; j++) { s[j] = __expf(s[j] - mx); sum += s[j]; }
    const float inv = __frcp_rn(sum);
#pragma unroll
    for (int j = 0; j < 8; j++) s[j] *= inv;

    // ---- AV: out[i, chunk c] = sum_j s[j] * v[j, chunk c] (smem broadcast) ----
    float o[16];
#pragma unroll
    for (int m = 0; m < 16; m++) o[m] = 0.f;
#pragma unroll
    for (int j = 0; j < 8; j++) {
        const float a = s[j];
#pragma unroll
        for (int m = 0; m < 4; m++) {
            const float4 t = wv[j * 4 + m];
            o[4*m]   = fmaf(a, t.x, o[4*m]);
            o[4*m+1] = fmaf(a, t.y, o[4*m+1]);
            o[4*m+2] = fmaf(a, t.z, o[4*m+2]);
            o[4*m+3] = fmaf(a, t.w, o[4*m+3]);
        }
    }

#pragma unroll
    for (int m = 0; m < 4; m++)
        out[qbase + m] = make_float4(o[4*m], o[4*m+1], o[4*m+2], o[4*m+3]);
}

extern "C" void kernel_launch(void* const* d_in, const int* in_sizes, int n_in,
                              void* d_out, int out_size)
{
    const float4* q = (const float4*)d_in[0];
    const float4* k = (const float4*)d_in[1];
    const float4* v = (const float4*)d_in[2];
    float4* o       = (float4*)d_out;
    // 256 threads = 8 warps; 2 warps (head groups) per position; 4 pos per CTA
    hilbert_headattn_kernel<<<NPOS / 4, 256>>>(q, k, v, o);
}

// round 12
// speedup vs baseline: 2.6482x; 1.4175x over previous
#include <cuda_runtime.h>

// q,k,v,out: (B=4, S=4096, H=16, D=64) f32. Hilbert gather + inverse scatter
// cancel (attention is strictly per-position): per (b,s) two independent 8x8
// head-vs-head attentions (groups of 8 heads), inner dim 64.
//
// R7: warp = position (covers BOTH groups). Lane (g=bit4, i1=bit3, c8=bits0-2)
// owns 4 rows {8g+4i1+t, t=0..3} of q/k/v over the 8-dim chunk
// {4*c8..4*c8+3} U {32+4*c8..+3} (float4 indices c8 and 8+c8 -> every LDG/STG
// fully coalesced: 4 rows x 128B contiguous). Each shuffled k/v chunk feeds
// 4 score rows => exchange per position drops from 256+256 shfl (R3) to 64+64.
// Score allreduce over the 8 c8-lanes = 96 shfl (pure adds). Softmax local.
#define NPOS  16384
#define SCALE 0.125f

__global__ __launch_bounds__(128)
void hilbert_headattn_kernel(const float4* __restrict__ q,
                             const float4* __restrict__ k,
                             const float4* __restrict__ v,
                             float4* __restrict__ out)
{
    const int lane = threadIdx.x & 31;
    const int pos  = blockIdx.x * 4 + (threadIdx.x >> 5);
    const int c8   = lane & 7;
    // rows owned: r(t) = (lane>>3)*4 + t  (== 8g + 4*i1 + t)
    // float4 index of (row r, half h): pos*256 + r*16 + h*8 + c8
    const int tb   = pos * 256 + ((lane >> 3) << 6) + c8;   // (lane>>3)*4*16

    // ---- load q (SCALE folded) and k ----
    float qr[4][8], kr[4][8];
#pragma unroll
    for (int t = 0; t < 4; t++) {
#pragma unroll
        for (int h = 0; h < 2; h++) {
            const int gi = tb + t * 16 + h * 8;
            float4 a = q[gi];
            qr[t][4*h]   = a.x * SCALE; qr[t][4*h+1] = a.y * SCALE;
            qr[t][4*h+2] = a.z * SCALE; qr[t][4*h+3] = a.w * SCALE;
            float4 b = k[gi];
            kr[t][4*h]   = b.x; kr[t][4*h+1] = b.y;
            kr[t][4*h+2] = b.z; kr[t][4*h+3] = b.w;
        }
    }

    // ---- partial scores: s[t][j] = q[r(t)] . k[8g+j] over this lane's chunk ----
    float s[4][8];
#pragma unroll
    for (int j = 0; j < 8; j++) {
        const int src = (lane & 0x17) | ((j >> 2) << 3);   // lane owning k row 8g+j
        float kb[8];
#pragma unroll
        for (int m = 0; m < 8; m++)
            kb[m] = __shfl_sync(0xffffffffu, kr[j & 3][m], src);
#pragma unroll
        for (int t = 0; t < 4; t++) {
            float acc = 0.f;
#pragma unroll
            for (int m = 0; m < 8; m++)
                acc = fmaf(qr[t][m], kb[m], acc);
            s[t][j] = acc;
        }
    }

    // ---- allreduce partials over the 8 c8-lanes (xor 1,2,4) ----
#pragma unroll
    for (int w = 1; w < 8; w <<= 1)
#pragma unroll
        for (int t = 0; t < 4; t++)
#pragma unroll
            for (int j = 0; j < 8; j++)
                s[t][j] += __shfl_xor_sync(0xffffffffu, s[t][j], w);

    // ---- load v now (after k retires; overlaps with softmax math) ----
    float vr[4][8];
#pragma unroll
    for (int t = 0; t < 4; t++) {
#pragma unroll
        for (int h = 0; h < 2; h++) {
            float4 b = v[tb + t * 16 + h * 8];
            vr[t][4*h]   = b.x; vr[t][4*h+1] = b.y;
            vr[t][4*h+2] = b.z; vr[t][4*h+3] = b.w;
        }
    }

    // ---- softmax over j, fully local per row ----
#pragma unroll
    for (int t = 0; t < 4; t++) {
        float mx = s[t][0];
#pragma unroll
        for (int j = 1; j < 8; j++) mx = fmaxf(mx, s[t][j]);
        float sum = 0.f;
#pragma unroll
        for (int j = 0; j < 8; j++) { s[t][j] = __expf(s[t][j] - mx); sum += s[t][j]; }
        const float inv = __frcp_rn(sum);
#pragma unroll
        for (int j = 0; j < 8; j++) s[t][j] *= inv;
    }

    // ---- AV: out[r(t), chunk] = sum_j A[t][j] * v[8g+j, chunk] ----
    float o[4][8];
#pragma unroll
    for (int t = 0; t < 4; t++)
#pragma unroll
        for (int m = 0; m < 8; m++) o[t][m] = 0.f;
#pragma unroll
    for (int j = 0; j < 8; j++) {
        const int src = (lane & 0x17) | ((j >> 2) << 3);
        float vb[8];
#pragma unroll
        for (int m = 0; m < 8; m++)
            vb[m] = __shfl_sync(0xffffffffu, vr[j & 3][m], src);
#pragma unroll
        for (int t = 0; t < 4; t++) {
            const float a = s[t][j];
#pragma unroll
            for (int m = 0; m < 8; m++)
                o[t][m] = fmaf(a, vb[m], o[t][m]);
        }
    }

#pragma unroll
    for (int t = 0; t < 4; t++) {
#pragma unroll
        for (int h = 0; h < 2; h++)
            out[tb + t * 16 + h * 8] =
                make_float4(o[t][4*h], o[t][4*h+1], o[t][4*h+2], o[t][4*h+3]);
    }
}

extern "C" void kernel_launch(void* const* d_in, const int* in_sizes, int n_in,
                              void* d_out, int out_size)
{
    const float4* q = (const float4*)d_in[0];
    const float4* k = (const float4*)d_in[1];
    const float4* v = (const float4*)d_in[2];
    float4* o       = (float4*)d_out;
    // 128 threads = 4 warps = 4 positions per CTA (1 warp per position)
    hilbert_headattn_kernel<<<NPOS / 4, 128>>>(q, k, v, o);
}

// round 13
// speedup vs baseline: 2.8701x; 1.0838x over previous
#include <cuda_runtime.h>

// q,k,v,out: (B=4, S=4096, H=16, D=64) f32. Hilbert gather + inverse scatter
// cancel (attention is strictly per-position): per (b,s) two independent 8x8
// head-vs-head attentions (groups of 8 heads), inner dim 64.
//
// R8 = R7 layout (warp = position; lane (g=bit4,i1=bit3,c8=bits0-2) owns rows
// {8g+4i1+t} over dim chunk {4c8..}{32+4c8..}) with k and v STREAMED in
// t-halves to cut peak regs ~127 -> ~100, buying a 5th CTA/SM (occupancy was
// the R7 limiter at DRAM=68%).
#define NPOS  16384
#define SCALE 0.125f

__global__ __launch_bounds__(128, 5)
void hilbert_headattn_kernel(const float4* __restrict__ q,
                             const float4* __restrict__ k,
                             const float4* __restrict__ v,
                             float4* __restrict__ out)
{
    const int lane = threadIdx.x & 31;
    const int pos  = blockIdx.x * 4 + (threadIdx.x >> 5);
    const int c8   = lane & 7;
    // float4 index of (owned row r = (lane>>3)*4 + t, half h): tb + t*16 + h*8
    const int tb   = pos * 256 + ((lane >> 3) << 6) + c8;

    // ---- q rows in registers, SCALE folded ----
    float qr[32];
#pragma unroll
    for (int t = 0; t < 4; t++)
#pragma unroll
        for (int h = 0; h < 2; h++) {
            const float4 a = q[tb + t * 16 + h * 8];
            qr[t*8+4*h]   = a.x * SCALE;
            qr[t*8+4*h+1] = a.y * SCALE;
            qr[t*8+4*h+2] = a.z * SCALE;
            qr[t*8+4*h+3] = a.w * SCALE;
        }

    float kr[16];
    float s[4][8];

    // ---- k half 1 (t=0,1) ; partial scores for j in {0,1,4,5} ----
#pragma unroll
    for (int t = 0; t < 2; t++)
#pragma unroll
        for (int h = 0; h < 2; h++) {
            const float4 b = k[tb + t * 16 + h * 8];
            kr[t*8+4*h]   = b.x; kr[t*8+4*h+1] = b.y;
            kr[t*8+4*h+2] = b.z; kr[t*8+4*h+3] = b.w;
        }
    {
        const int js[4] = {0, 1, 4, 5};
#pragma unroll
        for (int u = 0; u < 4; u++) {
            const int j   = js[u];
            const int src = (lane & 0x17) | ((j >> 2) << 3);
            float kb[8];
#pragma unroll
            for (int m = 0; m < 8; m++)
                kb[m] = __shfl_sync(0xffffffffu, kr[(j & 1) * 8 + m], src);
#pragma unroll
            for (int t = 0; t < 4; t++) {
                float acc = 0.f;
#pragma unroll
                for (int m = 0; m < 8; m++)
                    acc = fmaf(qr[t*8+m], kb[m], acc);
                s[t][j] = acc;
            }
        }
    }

    // ---- k half 2 (t=2,3) reusing kr ; partial scores for j in {2,3,6,7} ----
#pragma unroll
    for (int t = 0; t < 2; t++)
#pragma unroll
        for (int h = 0; h < 2; h++) {
            const float4 b = k[tb + (t + 2) * 16 + h * 8];
            kr[t*8+4*h]   = b.x; kr[t*8+4*h+1] = b.y;
            kr[t*8+4*h+2] = b.z; kr[t*8+4*h+3] = b.w;
        }
    {
        const int js[4] = {2, 3, 6, 7};
#pragma unroll
        for (int u = 0; u < 4; u++) {
            const int j   = js[u];
            const int src = (lane & 0x17) | ((j >> 2) << 3);
            float kb[8];
#pragma unroll
            for (int m = 0; m < 8; m++)
                kb[m] = __shfl_sync(0xffffffffu, kr[((j & 3) - 2) * 8 + m], src);
#pragma unroll
            for (int t = 0; t < 4; t++) {
                float acc = 0.f;
#pragma unroll
                for (int m = 0; m < 8; m++)
                    acc = fmaf(qr[t*8+m], kb[m], acc);
                s[t][j] = acc;
            }
        }
    }

    // ---- v half 1 (t=0,1): issue now so DRAM latency overlaps allreduce ----
    float vr[16];
#pragma unroll
    for (int t = 0; t < 2; t++)
#pragma unroll
        for (int h = 0; h < 2; h++) {
            const float4 b = v[tb + t * 16 + h * 8];
            vr[t*8+4*h]   = b.x; vr[t*8+4*h+1] = b.y;
            vr[t*8+4*h+2] = b.z; vr[t*8+4*h+3] = b.w;
        }

    // ---- allreduce partial scores over the 8 c8-lanes ----
#pragma unroll
    for (int w = 1; w < 8; w <<= 1)
#pragma unroll
        for (int t = 0; t < 4; t++)
#pragma unroll
            for (int j = 0; j < 8; j++)
                s[t][j] += __shfl_xor_sync(0xffffffffu, s[t][j], w);

    // ---- softmax over j, fully local per row ----
#pragma unroll
    for (int t = 0; t < 4; t++) {
        float mx = s[t][0];
#pragma unroll
        for (int j = 1; j < 8; j++) mx = fmaxf(mx, s[t][j]);
        float sum = 0.f;
#pragma unroll
        for (int j = 0; j < 8; j++) { s[t][j] = __expf(s[t][j] - mx); sum += s[t][j]; }
        const float inv = __frcp_rn(sum);
#pragma unroll
        for (int j = 0; j < 8; j++) s[t][j] *= inv;
    }

    // ---- AV half 1: j in {0,1,4,5} using v rows t=0,1 ----
    float o[32];
#pragma unroll
    for (int m = 0; m < 32; m++) o[m] = 0.f;
    {
        const int js[4] = {0, 1, 4, 5};
#pragma unroll
        for (int u = 0; u < 4; u++) {
            const int j   = js[u];
            const int src = (lane & 0x17) | ((j >> 2) << 3);
            float vb[8];
#pragma unroll
            for (int m = 0; m < 8; m++)
                vb[m] = __shfl_sync(0xffffffffu, vr[(j & 1) * 8 + m], src);
#pragma unroll
            for (int t = 0; t < 4; t++) {
                const float a = s[t][j];
#pragma unroll
                for (int m = 0; m < 8; m++)
                    o[t*8+m] = fmaf(a, vb[m], o[t*8+m]);
            }
        }
    }

    // ---- v half 2 (t=2,3) reusing vr ; AV half 2: j in {2,3,6,7} ----
#pragma unroll
    for (int t = 0; t < 2; t++)
#pragma unroll
        for (int h = 0; h < 2; h++) {
            const float4 b = v[tb + (t + 2) * 16 + h * 8];
            vr[t*8+4*h]   = b.x; vr[t*8+4*h+1] = b.y;
            vr[t*8+4*h+2] = b.z; vr[t*8+4*h+3] = b.w;
        }
    {
        const int js[4] = {2, 3, 6, 7};
#pragma unroll
        for (int u = 0; u < 4; u++) {
            const int j   = js[u];
            const int src = (lane & 0x17) | ((j >> 2) << 3);
            float vb[8];
#pragma unroll
            for (int m = 0; m < 8; m++)
                vb[m] = __shfl_sync(0xffffffffu, vr[((j & 3) - 2) * 8 + m], src);
#pragma unroll
            for (int t = 0; t < 4; t++) {
                const float a = s[t][j];
#pragma unroll
                for (int m = 0; m < 8; m++)
                    o[t*8+m] = fmaf(a, vb[m], o[t*8+m]);
            }
        }
    }

    // ---- coalesced stores ----
#pragma unroll
    for (int t = 0; t < 4; t++)
#pragma unroll
        for (int h = 0; h < 2; h++)
            out[tb + t * 16 + h * 8] =
                make_float4(o[t*8+4*h], o[t*8+4*h+1], o[t*8+4*h+2], o[t*8+4*h+3]);
}

extern "C" void kernel_launch(void* const* d_in, const int* in_sizes, int n_in,
                              void* d_out, int out_size)
{
    const float4* q = (const float4*)d_in[0];
    const float4* k = (const float4*)d_in[1];
    const float4* v = (const float4*)d_in[2];
    float4* o       = (float4*)d_out;
    // 128 threads = 4 warps = 4 positions per CTA (1 warp per position)
    hilbert_headattn_kernel<<<NPOS / 4, 128>>>(q, k, v, o);
}